// round 11
// baseline (speedup 1.0000x reference)
#include <cuda_runtime.h>
#include <cuda_fp16.h>
#include <cstdint>

// EEG_GAT_65901978190358 — round 11
// R9 base (direct register epilogue, fused block-0 attention) +
//  - coalesced A loads (R10 pattern, verified)
//  - A-load split: LDG issue BEFORE compute, pack+STS AFTER compute
//    => DRAM latency hidden under the MMA phase.

#define FDIM  250
#define BM    64
#define BN    256
#define BKF   64            // k-halves per chunk (128 B per smem row)
#define NCHUNK 4
#define NEG_SLOPE 0.2f

__device__ __align__(16) __half g_Bh[NCHUNK * 256 * BKF];  // pre-swizzled SMEM image of W^T (fp16)

// ---------------- helpers ----------------
__device__ __forceinline__ uint32_t smem_u32(const void* p) {
    uint32_t a;
    asm("{ .reg .u64 t; cvta.to.shared.u64 t, %1; cvt.u32.u64 %0, t; }" : "=r"(a) : "l"(p));
    return a;
}
__device__ __forceinline__ uint32_t pack_f16x2(float lo, float hi) {
    uint32_t r;
    asm("cvt.rn.f16x2.f32 %0, %1, %2;" : "=r"(r) : "f"(hi), "f"(lo));
    return r;
}
__device__ __forceinline__ void sts_b32(uint32_t addr, uint32_t v) {
    asm volatile("st.shared.b32 [%0], %1;" :: "r"(addr), "r"(v) : "memory");
}
__device__ __forceinline__ void cp_async16(uint32_t smem_addr, const void* gptr) {
    asm volatile("cp.async.cg.shared.global [%0], [%1], 16;" :: "r"(smem_addr), "l"(gptr) : "memory");
}
__device__ __forceinline__ void ldmx4(uint32_t* r, uint32_t addr) {
    asm volatile("ldmatrix.sync.aligned.m8n8.x4.shared.b16 {%0,%1,%2,%3}, [%4];"
                 : "=r"(r[0]), "=r"(r[1]), "=r"(r[2]), "=r"(r[3]) : "r"(addr));
}
__device__ __forceinline__ void mma_f16(float* c, const uint32_t* a, uint32_t b0, uint32_t b1) {
    asm volatile(
        "mma.sync.aligned.m16n8k16.row.col.f32.f16.f16.f32 "
        "{%0,%1,%2,%3}, {%4,%5,%6,%7}, {%8,%9}, {%0,%1,%2,%3};"
        : "+f"(c[0]), "+f"(c[1]), "+f"(c[2]), "+f"(c[3])
        : "r"(a[0]), "r"(a[1]), "r"(a[2]), "r"(a[3]), "r"(b0), "r"(b1));
}

// ---------------- prep: g_Bh = pre-swizzled fp16 SMEM image of W^T ----------------
__global__ void prep_Bh(const float* __restrict__ W) {
    int idx = blockIdx.x * 256 + threadIdx.x;      // 65536 total
    int c  = idx >> 14;
    int n  = (idx >> 6) & 255;
    int kk = idx & 63;
    int k  = c * BKF + kk;
    float v = (n < FDIM && k < FDIM) ? W[k * FDIM + n] : 0.f;
    int dst = n * BKF + (kk & 7) + 8 * ((kk >> 3) ^ (n & 7));
    g_Bh[c * (256 * BKF) + dst] = __float2half_rn(v);
}

// ---------------- main GEMM + fused block-0 attention ----------------
__global__ __launch_bounds__(256, 2)
void gemm_h16(const float* __restrict__ X, const float* __restrict__ bias,
              const float* __restrict__ att_src, const float* __restrict__ att_dst,
              float* __restrict__ out, int nrows) {
    extern __shared__ __align__(16) char dsmem[];
    __shared__ float s_bias[256];
    __shared__ float s_as[64];
    __shared__ float s_ad[64];
    __shared__ float s_alpha[8][64];

    const int tid  = threadIdx.x;
    const int wid  = tid >> 5, lane = tid & 31;
    const int q    = lane >> 2, tig = lane & 3;
    const int wr   = wid >> 2, wc = wid & 3;       // warp grid 2 x 4 (m x n)
    const long row0 = (long)blockIdx.x * BM;
    const bool blk0 = (blockIdx.x == 0);

    const uint32_t sb = smem_u32(dsmem);
    const uint32_t Au[2] = { sb,          sb + 8192 };              // 64*128 B each
    const uint32_t Bu[2] = { sb + 16384,  sb + 16384 + 32768 };     // 256*128 B each
    float* h64 = reinterpret_cast<float*>(dsmem);   // block 0: [64][256] after mainloop

    s_bias[tid] = (tid < FDIM) ? bias[tid] : 0.f;

    // A loader: warp per 8 rows; lane covers float2 at k = 2*lane within chunk
    const float* xbase = X + (row0 + wid * 8) * FDIM + 2 * lane;
    const bool arowok[1] = { true };  // (kept simple; bounds in loads)

    // ldmatrix per-lane geometry
    const int a_mrow = ((lane >> 3) & 1) * 8 + (lane & 7);
    const int a_chb  = (lane >> 4);
    const int b_nrow = (lane >> 4) * 8 + (lane & 7);
    const int b_chb  = ((lane >> 3) & 1);

    float acc[2][8][4];
    #pragma unroll
    for (int mt = 0; mt < 2; ++mt)
        #pragma unroll
        for (int nt = 0; nt < 8; ++nt)
            #pragma unroll
            for (int e = 0; e < 4; ++e) acc[mt][nt][e] = 0.f;

    float2 pa[8];     // A prefetch registers (live across COMPUTE)

    #define LOAD_B(cc, buf) do {                                                    \
        const char* src = (const char*)g_Bh + (size_t)(cc) * 32768;                  \
        _Pragma("unroll")                                                            \
        for (int v8 = 0; v8 < 8; ++v8) {                                             \
            int i = v8 * 256 + tid;                                                  \
            cp_async16(Bu[buf] + i * 16, src + i * 16);                              \
        }                                                                            \
    } while (0)

    // issue LDGs only (results land in pa[]) — no stall here
    #define PREF_A(cc) do {                                                          \
        const int kk = (cc) * BKF + 2 * lane;                                        \
        const bool kok = (kk + 1) < FDIM;                                            \
        _Pragma("unroll")                                                            \
        for (int rr = 0; rr < 8; ++rr) {                                             \
            int r = wid * 8 + rr;                                                    \
            pa[rr] = make_float2(0.f, 0.f);                                          \
            if (kok && (row0 + r) < nrows)                                           \
                pa[rr] = *reinterpret_cast<const float2*>(xbase + rr * FDIM + (cc) * BKF); \
        }                                                                            \
    } while (0)

    // pack + STS (stalls on the LDGs, which by now overlapped COMPUTE)
    #define STORE_A(buf) do {                                                        \
        _Pragma("unroll")                                                            \
        for (int rr = 0; rr < 8; ++rr) {                                             \
            int r = wid * 8 + rr;                                                    \
            uint32_t hv = pack_f16x2(pa[rr].x, pa[rr].y);                            \
            uint32_t addr = Au[buf] + r * 128 +                                      \
                            (((lane >> 2) ^ (r & 7)) << 4) + ((lane & 3) << 2);      \
            sts_b32(addr, hv);                                                       \
        }                                                                            \
    } while (0)

    #define COMPUTE(buf) do {                                                        \
        _Pragma("unroll")                                                             \
        for (int g = 0; g < 4; ++g) {                                                 \
            uint32_t a[2][4];                                                         \
            _Pragma("unroll")                                                         \
            for (int mt = 0; mt < 2; ++mt) {                                          \
                int r = wr * 32 + mt * 16 + a_mrow;                                   \
                int ch = 2 * g + a_chb;                                               \
                ldmx4(a[mt], Au[buf] + r * 128 + ((ch ^ (r & 7)) << 4));              \
            }                                                                         \
            _Pragma("unroll")                                                         \
            for (int p = 0; p < 4; ++p) {                                             \
                uint32_t b[4];                                                        \
                int r = wc * 64 + p * 16 + b_nrow;                                    \
                int ch = 2 * g + b_chb;                                               \
                ldmx4(b, Bu[buf] + r * 128 + ((ch ^ (r & 7)) << 4));                  \
                mma_f16(acc[0][2 * p],     a[0], b[0], b[1]);                         \
                mma_f16(acc[0][2 * p + 1], a[0], b[2], b[3]);                         \
                mma_f16(acc[1][2 * p],     a[1], b[0], b[1]);                         \
                mma_f16(acc[1][2 * p + 1], a[1], b[2], b[3]);                         \
            }                                                                         \
        }                                                                             \
    } while (0)

    // ---- prologue: chunk 0 ----
    LOAD_B(0, 0);
    asm volatile("cp.async.commit_group;" ::: "memory");
    PREF_A(0);
    STORE_A(0);
    asm volatile("cp.async.wait_group 0;" ::: "memory");
    __syncthreads();

    // ---- mainloop: double-buffered, A-latency overlapped with COMPUTE ----
    #pragma unroll
    for (int c = 0; c < NCHUNK; ++c) {
        int buf = c & 1;
        if (c < NCHUNK - 1) {
            LOAD_B(c + 1, buf ^ 1);
            asm volatile("cp.async.commit_group;" ::: "memory");
            PREF_A(c + 1);
        }
        COMPUTE(buf);
        if (c < NCHUNK - 1) {
            STORE_A(buf ^ 1);
            asm volatile("cp.async.wait_group 0;" ::: "memory");
            __syncthreads();
        }
    }

    // block 0 reuses pipeline smem for h rows 0..62 — wait until all warps done
    if (blk0) __syncthreads();

    // ---- epilogue: direct register stores (+bias); blk0 rows<63 staged in smem ----
    #pragma unroll
    for (int mt = 0; mt < 2; ++mt) {
        long r0 = row0 + wr * 32 + mt * 16 + q;
        long r1 = r0 + 8;
        #pragma unroll
        for (int nt = 0; nt < 8; ++nt) {
            int j = wc * 64 + nt * 8 + 2 * tig;    // even
            if (j + 1 >= FDIM) continue;
            float* a4 = acc[mt][nt];
            if (r0 < nrows) {
                if (r0 < 63)
                    *reinterpret_cast<float2*>(&h64[r0 * 256 + j]) = make_float2(a4[0], a4[1]);
                else
                    *reinterpret_cast<float2*>(out + r0 * FDIM + j) =
                        make_float2(a4[0] + s_bias[j], a4[1] + s_bias[j + 1]);
            }
            if (r1 < nrows) {
                if (r1 < 63)
                    *reinterpret_cast<float2*>(&h64[r1 * 256 + j]) = make_float2(a4[2], a4[3]);
                else
                    *reinterpret_cast<float2*>(out + r1 * FDIM + j) =
                        make_float2(a4[2] + s_bias[j], a4[3] + s_bias[j + 1]);
            }
        }
    }

    if (!blk0) return;

    // ================= block 0: dense 63x63 attention =================
    __syncthreads();   // h64 visible

    for (int i = wid; i < 63; i += 8) {
        float s1 = 0.f, s2 = 0.f;
        for (int k = lane; k < FDIM; k += 32) {
            float hv = h64[i * 256 + k];
            s1 += hv * att_src[k];
            s2 += hv * att_dst[k];
        }
        #pragma unroll
        for (int o = 16; o > 0; o >>= 1) {
            s1 += __shfl_xor_sync(0xffffffffu, s1, o);
            s2 += __shfl_xor_sync(0xffffffffu, s2, o);
        }
        if (lane == 0) { s_as[i] = s1; s_ad[i] = s2; }
    }
    __syncthreads();

    for (int j = wid; j < 63; j += 8) {
        float ad = s_ad[j];
        float e0 = s_as[lane] + ad;
        e0 = (e0 >= 0.f) ? e0 : NEG_SLOPE * e0;
        float e1 = -3.4e38f;
        if (lane < 31) {
            e1 = s_as[lane + 32] + ad;
            e1 = (e1 >= 0.f) ? e1 : NEG_SLOPE * e1;
        }
        float m = fmaxf(e0, e1);
        #pragma unroll
        for (int o = 16; o > 0; o >>= 1) m = fmaxf(m, __shfl_xor_sync(0xffffffffu, m, o));
        float x0 = expf(e0 - m);
        float x1 = (lane < 31) ? expf(e1 - m) : 0.f;
        float sum = x0 + x1;
        #pragma unroll
        for (int o = 16; o > 0; o >>= 1) sum += __shfl_xor_sync(0xffffffffu, sum, o);
        float inv = 1.f / sum;
        s_alpha[wid][lane]      = x0 * inv;
        s_alpha[wid][lane + 32] = x1 * inv;
        __syncwarp();

        for (int t = lane; t < FDIM; t += 32) {
            float a = 0.f;
            #pragma unroll
            for (int i = 0; i < 63; ++i)
                a = fmaf(s_alpha[wid][i], h64[i * 256 + t], a);
            out[(size_t)j * FDIM + t] = a + s_bias[t];
        }
        __syncwarp();
    }
}

extern "C" void kernel_launch(void* const* d_in, const int* in_sizes, int n_in,
                              void* d_out, int out_size) {
    const float* x       = (const float*)d_in[0];
    const float* W       = (const float*)d_in[1];
    const float* att_src = (const float*)d_in[2];
    const float* att_dst = (const float*)d_in[3];
    const float* bias    = (const float*)d_in[4];
    float* out = (float*)d_out;

    const int nrows = in_sizes[0] / FDIM;                 // 258048
    const int smem_dyn = 16384 + 2 * 32768;               // 80 KB

    static int configured = 0;
    if (!configured) {
        cudaFuncSetAttribute(gemm_h16, cudaFuncAttributeMaxDynamicSharedMemorySize, smem_dyn);
        configured = 1;
    }

    prep_Bh<<<256, 256>>>(W);
    gemm_h16<<<(nrows + BM - 1) / BM, 256, smem_dyn>>>(x, bias, att_src, att_dst, out, nrows);
}

// round 12
// speedup vs baseline: 1.0781x; 1.0781x over previous
#include <cuda_runtime.h>
#include <cuda_fp16.h>
#include <cstdint>

// EEG_GAT_65901978190358 — round 12
// Occupancy attack: CTA tile 64x128 (warp tile 32x32, ~80 regs) => 3 CTAs/SM.
// grid(2, 4032): the two j-tiles of a row block are linearly adjacent so the
// second one's X reads hit L2 (X DRAM read stays 1x). Attention becomes a
// two-block handoff via atomic counter on the by==0 pair (self-resetting,
// graph-replay safe), reading h63 from a global scratch.

#define FDIM  250
#define BM    64
#define BN    128
#define BKF   64            // k-halves per chunk (128 B per smem row)
#define NCHUNK 4
#define NEG_SLOPE 0.2f

__device__ __align__(16) __half g_Bh[NCHUNK * 256 * BKF];  // pre-swizzled SMEM image of W^T (fp16)
__device__ __align__(16) float g_h63[63 * 256];            // h rows 0..62, pitch 256
__device__ int g_ctr = 0;

// ---------------- helpers ----------------
__device__ __forceinline__ uint32_t smem_u32(const void* p) {
    uint32_t a;
    asm("{ .reg .u64 t; cvta.to.shared.u64 t, %1; cvt.u32.u64 %0, t; }" : "=r"(a) : "l"(p));
    return a;
}
__device__ __forceinline__ uint32_t pack_f16x2(float lo, float hi) {
    uint32_t r;
    asm("cvt.rn.f16x2.f32 %0, %1, %2;" : "=r"(r) : "f"(hi), "f"(lo));
    return r;
}
__device__ __forceinline__ void sts_b32(uint32_t addr, uint32_t v) {
    asm volatile("st.shared.b32 [%0], %1;" :: "r"(addr), "r"(v) : "memory");
}
__device__ __forceinline__ void cp_async16(uint32_t smem_addr, const void* gptr) {
    asm volatile("cp.async.cg.shared.global [%0], [%1], 16;" :: "r"(smem_addr), "l"(gptr) : "memory");
}
__device__ __forceinline__ void ldmx4(uint32_t* r, uint32_t addr) {
    asm volatile("ldmatrix.sync.aligned.m8n8.x4.shared.b16 {%0,%1,%2,%3}, [%4];"
                 : "=r"(r[0]), "=r"(r[1]), "=r"(r[2]), "=r"(r[3]) : "r"(addr));
}
__device__ __forceinline__ void mma_f16(float* c, const uint32_t* a, uint32_t b0, uint32_t b1) {
    asm volatile(
        "mma.sync.aligned.m16n8k16.row.col.f32.f16.f16.f32 "
        "{%0,%1,%2,%3}, {%4,%5,%6,%7}, {%8,%9}, {%0,%1,%2,%3};"
        : "+f"(c[0]), "+f"(c[1]), "+f"(c[2]), "+f"(c[3])
        : "r"(a[0]), "r"(a[1]), "r"(a[2]), "r"(a[3]), "r"(b0), "r"(b1));
}

// ---------------- prep: g_Bh = pre-swizzled fp16 SMEM image of W^T ----------------
__global__ void prep_Bh(const float* __restrict__ W) {
    int idx = blockIdx.x * 256 + threadIdx.x;      // 65536 total
    int c  = idx >> 14;
    int n  = (idx >> 6) & 255;
    int kk = idx & 63;
    int k  = c * BKF + kk;
    float v = (n < FDIM && k < FDIM) ? W[k * FDIM + n] : 0.f;
    int dst = n * BKF + (kk & 7) + 8 * ((kk >> 3) ^ (n & 7));
    g_Bh[c * (256 * BKF) + dst] = __float2half_rn(v);
}

// ---------------- main GEMM + handoff attention ----------------
__global__ __launch_bounds__(256, 3)
void gemm_h16(const float* __restrict__ X, const float* __restrict__ bias,
              const float* __restrict__ att_src, const float* __restrict__ att_dst,
              float* __restrict__ out, int nrows) {
    extern __shared__ __align__(16) char dsmem[];
    __shared__ float s_bias[128];
    __shared__ float s_as[64];
    __shared__ float s_ad[64];
    __shared__ float s_alpha[8][64];
    __shared__ int s_go;

    const int tid  = threadIdx.x;
    const int wid  = tid >> 5, lane = tid & 31;
    const int q    = lane >> 2, tig = lane & 3;
    const int wr   = wid >> 2, wc = wid & 3;       // warp grid 2 x 4 (m x n of 32x32 tiles)
    const int bx   = blockIdx.x;                   // j-tile 0/1
    const long row0 = (long)blockIdx.y * BM;
    const int jbase = bx * BN;

    const uint32_t sb = smem_u32(dsmem);
    const uint32_t Au[2] = { sb,          sb + 8192 };           // 64*128 B each
    const uint32_t Bu[2] = { sb + 16384,  sb + 16384 + 16384 };  // 128*128 B each

    if (tid < 128) s_bias[tid] = (jbase + tid < FDIM) ? bias[jbase + tid] : 0.f;

    // A loader: warp per 8 rows; lane covers float2 at k = 2*lane within chunk
    const float* xbase = X + (row0 + wid * 8) * FDIM + 2 * lane;

    // ldmatrix per-lane geometry
    const int a_mrow = ((lane >> 3) & 1) * 8 + (lane & 7);
    const int a_chb  = (lane >> 4);
    const int b_nrow = (lane >> 4) * 8 + (lane & 7);
    const int b_chb  = ((lane >> 3) & 1);

    float acc[2][4][4];
    #pragma unroll
    for (int mt = 0; mt < 2; ++mt)
        #pragma unroll
        for (int nt = 0; nt < 4; ++nt)
            #pragma unroll
            for (int e = 0; e < 4; ++e) acc[mt][nt][e] = 0.f;

    #define LOAD_B(cc, buf) do {                                                    \
        const char* src = (const char*)g_Bh + (size_t)(cc) * 32768 + (size_t)bx * 16384; \
        _Pragma("unroll")                                                            \
        for (int v4 = 0; v4 < 4; ++v4) {                                             \
            int i = v4 * 256 + tid;                                                  \
            cp_async16(Bu[buf] + i * 16, src + i * 16);                              \
        }                                                                            \
    } while (0)

    #define LOAD_A(cc, buf) do {                                                     \
        const int kk = (cc) * BKF + 2 * lane;                                        \
        const bool kok = (kk + 1) < FDIM;                                            \
        _Pragma("unroll")                                                            \
        for (int rr = 0; rr < 8; ++rr) {                                             \
            int r = wid * 8 + rr;                                                    \
            float2 t = make_float2(0.f, 0.f);                                        \
            if (kok && (row0 + r) < nrows)                                           \
                t = *reinterpret_cast<const float2*>(xbase + rr * FDIM + (cc) * BKF);\
            uint32_t hv = pack_f16x2(t.x, t.y);                                      \
            uint32_t addr = Au[buf] + r * 128 +                                      \
                            (((lane >> 2) ^ (r & 7)) << 4) + ((lane & 3) << 2);      \
            sts_b32(addr, hv);                                                       \
        }                                                                            \
    } while (0)

    #define COMPUTE(buf) do {                                                        \
        _Pragma("unroll")                                                             \
        for (int g = 0; g < 4; ++g) {                                                 \
            uint32_t a[2][4];                                                         \
            _Pragma("unroll")                                                         \
            for (int mt = 0; mt < 2; ++mt) {                                          \
                int r = wr * 32 + mt * 16 + a_mrow;                                   \
                int ch = 2 * g + a_chb;                                               \
                ldmx4(a[mt], Au[buf] + r * 128 + ((ch ^ (r & 7)) << 4));              \
            }                                                                         \
            _Pragma("unroll")                                                         \
            for (int p = 0; p < 2; ++p) {                                             \
                uint32_t b[4];                                                        \
                int r = wc * 32 + p * 16 + b_nrow;                                    \
                int ch = 2 * g + b_chb;                                               \
                ldmx4(b, Bu[buf] + r * 128 + ((ch ^ (r & 7)) << 4));                  \
                mma_f16(acc[0][2 * p],     a[0], b[0], b[1]);                         \
                mma_f16(acc[0][2 * p + 1], a[0], b[2], b[3]);                         \
                mma_f16(acc[1][2 * p],     a[1], b[0], b[1]);                         \
                mma_f16(acc[1][2 * p + 1], a[1], b[2], b[3]);                         \
            }                                                                         \
        }                                                                             \
    } while (0)

    // ---- pipeline: double-buffered over 4 K-chunks ----
    LOAD_B(0, 0);
    asm volatile("cp.async.commit_group;" ::: "memory");
    LOAD_A(0, 0);
    asm volatile("cp.async.wait_group 0;" ::: "memory");
    __syncthreads();

    #pragma unroll
    for (int c = 0; c < NCHUNK; ++c) {
        int buf = c & 1;
        if (c < NCHUNK - 1) {
            LOAD_B(c + 1, buf ^ 1);
            asm volatile("cp.async.commit_group;" ::: "memory");
            LOAD_A(c + 1, buf ^ 1);
        }
        COMPUTE(buf);
        if (c < NCHUNK - 1) {
            asm volatile("cp.async.wait_group 0;" ::: "memory");
            __syncthreads();
        }
    }

    // ---- epilogue: direct register stores (+bias); rows<63 -> g_h63 scratch ----
    #pragma unroll
    for (int mt = 0; mt < 2; ++mt) {
        long r0 = row0 + wr * 32 + mt * 16 + q;
        long r1 = r0 + 8;
        #pragma unroll
        for (int nt = 0; nt < 4; ++nt) {
            int jl = wc * 32 + nt * 8 + 2 * tig;   // even, < 128
            int jg = jbase + jl;
            if (jg + 1 >= FDIM) continue;
            float* a4 = acc[mt][nt];
            if (r0 < nrows) {
                if (r0 < 63)
                    *reinterpret_cast<float2*>(&g_h63[r0 * 256 + jg]) = make_float2(a4[0], a4[1]);
                else
                    *reinterpret_cast<float2*>(out + r0 * FDIM + jg) =
                        make_float2(a4[0] + s_bias[jl], a4[1] + s_bias[jl + 1]);
            }
            if (r1 < nrows) {
                if (r1 < 63)
                    *reinterpret_cast<float2*>(&g_h63[r1 * 256 + jg]) = make_float2(a4[2], a4[3]);
                else
                    *reinterpret_cast<float2*>(out + r1 * FDIM + jg) =
                        make_float2(a4[2] + s_bias[jl], a4[3] + s_bias[jl + 1]);
            }
        }
    }

    if (blockIdx.y != 0) return;

    // ---- handoff: second arriver of the two by==0 blocks runs the attention ----
    __threadfence();
    if (tid == 0) s_go = (atomicAdd(&g_ctr, 1) == 1) ? 1 : 0;
    __syncthreads();
    if (!s_go) return;

    // ================= dense 63x63 attention over g_h63 =================
    for (int i = wid; i < 63; i += 8) {
        float s1 = 0.f, s2 = 0.f;
        for (int k = lane; k < FDIM; k += 32) {
            float hv = g_h63[i * 256 + k];
            s1 += hv * att_src[k];
            s2 += hv * att_dst[k];
        }
        #pragma unroll
        for (int o = 16; o > 0; o >>= 1) {
            s1 += __shfl_xor_sync(0xffffffffu, s1, o);
            s2 += __shfl_xor_sync(0xffffffffu, s2, o);
        }
        if (lane == 0) { s_as[i] = s1; s_ad[i] = s2; }
    }
    __syncthreads();

    for (int j = wid; j < 63; j += 8) {
        float ad = s_ad[j];
        float e0 = s_as[lane] + ad;
        e0 = (e0 >= 0.f) ? e0 : NEG_SLOPE * e0;
        float e1 = -3.4e38f;
        if (lane < 31) {
            e1 = s_as[lane + 32] + ad;
            e1 = (e1 >= 0.f) ? e1 : NEG_SLOPE * e1;
        }
        float m = fmaxf(e0, e1);
        #pragma unroll
        for (int o = 16; o > 0; o >>= 1) m = fmaxf(m, __shfl_xor_sync(0xffffffffu, m, o));
        float x0 = expf(e0 - m);
        float x1 = (lane < 31) ? expf(e1 - m) : 0.f;
        float sum = x0 + x1;
        #pragma unroll
        for (int o = 16; o > 0; o >>= 1) sum += __shfl_xor_sync(0xffffffffu, sum, o);
        float inv = 1.f / sum;
        s_alpha[wid][lane]      = x0 * inv;
        s_alpha[wid][lane + 32] = x1 * inv;
        __syncwarp();

        for (int t = lane; t < FDIM; t += 32) {
            float a = 0.f;
            #pragma unroll
            for (int i = 0; i < 63; ++i)
                a = fmaf(s_alpha[wid][i], g_h63[i * 256 + t], a);
            out[(size_t)j * FDIM + t] = a + bias[t];
        }
        __syncwarp();
    }

    __syncthreads();
    if (tid == 0) g_ctr = 0;   // reset for next graph replay
}

extern "C" void kernel_launch(void* const* d_in, const int* in_sizes, int n_in,
                              void* d_out, int out_size) {
    const float* x       = (const float*)d_in[0];
    const float* W       = (const float*)d_in[1];
    const float* att_src = (const float*)d_in[2];
    const float* att_dst = (const float*)d_in[3];
    const float* bias    = (const float*)d_in[4];
    float* out = (float*)d_out;

    const int nrows = in_sizes[0] / FDIM;                 // 258048
    const int smem_dyn = 16384 + 2 * 16384;               // A 2x8K + B 2x16K = 48 KB

    static int configured = 0;
    if (!configured) {
        cudaFuncSetAttribute(gemm_h16, cudaFuncAttributeMaxDynamicSharedMemorySize, smem_dyn);
        configured = 1;
    }

    prep_Bh<<<256, 256>>>(W);
    dim3 grid(2, (nrows + BM - 1) / BM);                  // (2, 4032), j-tiles adjacent
    gemm_h16<<<grid, 256, smem_dyn>>>(x, bias, att_src, att_dst, out, nrows);
}

// round 14
// speedup vs baseline: 1.2988x; 1.2047x over previous
#include <cuda_runtime.h>
#include <cuda_fp16.h>
#include <cstdint>

// EEG_GAT_65901978190358 — round 14
// R13 with the misalignment fix: A staging uses 8-byte cp.async.ca
// (X row pitch = 1000 B is only 8B-aligned). Conflict-free CONVERT mapping.
// R9 config otherwise: 64x256 tile, 2 CTAs/SM, fused block-0 attention.

#define FDIM  250
#define BM    64
#define BN    256
#define BKF   64            // k-values per chunk
#define NCHUNK 4
#define NEG_SLOPE 0.2f

__device__ __align__(16) __half g_Bh[NCHUNK * 256 * BKF];  // pre-swizzled SMEM image of W^T (fp16)

// ---------------- helpers ----------------
__device__ __forceinline__ uint32_t smem_u32(const void* p) {
    uint32_t a;
    asm("{ .reg .u64 t; cvta.to.shared.u64 t, %1; cvt.u32.u64 %0, t; }" : "=r"(a) : "l"(p));
    return a;
}
__device__ __forceinline__ uint32_t pack_f16x2(float lo, float hi) {
    uint32_t r;
    asm("cvt.rn.f16x2.f32 %0, %1, %2;" : "=r"(r) : "f"(hi), "f"(lo));
    return r;
}
__device__ __forceinline__ void sts_v2(uint32_t addr, uint32_t a, uint32_t b) {
    asm volatile("st.shared.v2.b32 [%0], {%1, %2};" :: "r"(addr), "r"(a), "r"(b) : "memory");
}
__device__ __forceinline__ void lds_v4(float& a, float& b, float& c, float& d, uint32_t addr) {
    asm volatile("ld.shared.v4.f32 {%0, %1, %2, %3}, [%4];"
                 : "=f"(a), "=f"(b), "=f"(c), "=f"(d) : "r"(addr));
}
__device__ __forceinline__ void cp_async16(uint32_t smem_addr, const void* gptr) {
    asm volatile("cp.async.cg.shared.global [%0], [%1], 16;" :: "r"(smem_addr), "l"(gptr) : "memory");
}
__device__ __forceinline__ void cp_async8(uint32_t smem_addr, const void* gptr) {
    asm volatile("cp.async.ca.shared.global [%0], [%1], 8;" :: "r"(smem_addr), "l"(gptr) : "memory");
}
__device__ __forceinline__ void ldmx4(uint32_t* r, uint32_t addr) {
    asm volatile("ldmatrix.sync.aligned.m8n8.x4.shared.b16 {%0,%1,%2,%3}, [%4];"
                 : "=r"(r[0]), "=r"(r[1]), "=r"(r[2]), "=r"(r[3]) : "r"(addr));
}
__device__ __forceinline__ void mma_f16(float* c, const uint32_t* a, uint32_t b0, uint32_t b1) {
    asm volatile(
        "mma.sync.aligned.m16n8k16.row.col.f32.f16.f16.f32 "
        "{%0,%1,%2,%3}, {%4,%5,%6,%7}, {%8,%9}, {%0,%1,%2,%3};"
        : "+f"(c[0]), "+f"(c[1]), "+f"(c[2]), "+f"(c[3])
        : "r"(a[0]), "r"(a[1]), "r"(a[2]), "r"(a[3]), "r"(b0), "r"(b1));
}

// ---------------- prep: g_Bh = pre-swizzled fp16 SMEM image of W^T ----------------
__global__ void prep_Bh(const float* __restrict__ W) {
    int idx = blockIdx.x * 256 + threadIdx.x;      // 65536 total
    int c  = idx >> 14;
    int n  = (idx >> 6) & 255;
    int kk = idx & 63;
    int k  = c * BKF + kk;
    float v = (n < FDIM && k < FDIM) ? W[k * FDIM + n] : 0.f;
    int dst = n * BKF + (kk & 7) + 8 * ((kk >> 3) ^ (n & 7));
    g_Bh[c * (256 * BKF) + dst] = __float2half_rn(v);
}

// ---------------- main GEMM + fused block-0 attention ----------------
__global__ __launch_bounds__(256, 2)
void gemm_h16(const float* __restrict__ X, const float* __restrict__ bias,
              const float* __restrict__ att_src, const float* __restrict__ att_dst,
              float* __restrict__ out, int nrows) {
    extern __shared__ __align__(16) char dsmem[];
    __shared__ float s_bias[256];
    __shared__ float s_as[64];
    __shared__ float s_ad[64];
    __shared__ float s_alpha[8][64];

    const int tid  = threadIdx.x;
    const int wid  = tid >> 5, lane = tid & 31;
    const int q    = lane >> 2, tig = lane & 3;
    const int wr   = wid >> 2, wc = wid & 3;       // warp grid 2 x 4 (m x n)
    const long row0 = (long)blockIdx.x * BM;
    const bool blk0 = (blockIdx.x == 0);

    const uint32_t sb = smem_u32(dsmem);
    // layout: A32[2] (2x16K) | A16 (8K) | B[2] (2x32K)  = 104 KB
    const uint32_t A32[2] = { sb,        sb + 16384 };
    const uint32_t A16    =   sb + 32768;
    const uint32_t Bu[2]  = { sb + 40960, sb + 73728 };
    float* h64 = reinterpret_cast<float*>(dsmem);   // block 0 alias after mainloop

    s_bias[tid] = (tid < FDIM) ? bias[tid] : 0.f;

    // ldmatrix per-lane geometry
    const int a_mrow = ((lane >> 3) & 1) * 8 + (lane & 7);
    const int a_chb  = (lane >> 4);
    const int b_nrow = (lane >> 4) * 8 + (lane & 7);
    const int b_chb  = ((lane >> 3) & 1);

    float acc[2][8][4];
    #pragma unroll
    for (int mt = 0; mt < 2; ++mt)
        #pragma unroll
        for (int nt = 0; nt < 8; ++nt)
            #pragma unroll
            for (int e = 0; e < 4; ++e) acc[mt][nt][e] = 0.f;

    #define LOAD_B(cc, buf) do {                                                    \
        const char* src = (const char*)g_Bh + (size_t)(cc) * 32768;                  \
        _Pragma("unroll")                                                            \
        for (int v8 = 0; v8 < 8; ++v8) {                                             \
            int i = v8 * 256 + tid;                                                  \
            cp_async16(Bu[buf] + i * 16, src + i * 16);                              \
        }                                                                            \
    } while (0)

    // async A: 64 rows x 256 B per chunk, 8-byte segments (X rows are 8B-aligned).
    // warp covers one row's 32 contiguous segments => coalesced.
    // chunk 3: segs >= 29 skipped (k >= 250); stale smem annihilated by B zero pad.
    #define LOAD_A32(cc, buf) do {                                                   \
        _Pragma("unroll")                                                            \
        for (int v8 = 0; v8 < 8; ++v8) {                                             \
            int i = v8 * 256 + tid;                                                  \
            int r = i >> 5, seg = i & 31;                                            \
            if (((cc) < 3 || seg < 29) && (row0 + r) < nrows) {                      \
                const char* src = (const char*)X + (size_t)(row0 + r) * (FDIM * 4)   \
                                + (cc) * 256 + seg * 8;                              \
                cp_async8(A32[buf] + r * 256 + seg * 8, src);                        \
            }                                                                        \
        }                                                                            \
    } while (0)

    // fp32 smem -> fp16 smem (swizzled). Lane-contiguous pieces: each LDS.128
    // wavefront reads 512 contiguous bytes => conflict-free.
    #define CONVERT_A(buf) do {                                                      \
        _Pragma("unroll")                                                            \
        for (int j = 0; j < 4; ++j) {                                                \
            int o = j * 4096 + tid * 16;   /* byte offset in 16KB chunk staging */   \
            int r = o >> 8;                                                          \
            int b = o & 255;                                                         \
            float f0, f1, f2, f3;                                                    \
            lds_v4(f0, f1, f2, f3, A32[buf] + o);                                    \
            uint32_t h0 = pack_f16x2(f0, f1);                                        \
            uint32_t h1 = pack_f16x2(f2, f3);                                        \
            int hb = b >> 1;                                                         \
            int ch = hb >> 4, off = hb & 15;                                         \
            sts_v2(A16 + r * 128 + ((ch ^ (r & 7)) << 4) + off, h0, h1);             \
        }                                                                            \
    } while (0)

    #define COMPUTE(buf) do {                                                        \
        _Pragma("unroll")                                                             \
        for (int g = 0; g < 4; ++g) {                                                 \
            uint32_t a[2][4];                                                         \
            _Pragma("unroll")                                                         \
            for (int mt = 0; mt < 2; ++mt) {                                          \
                int r = wr * 32 + mt * 16 + a_mrow;                                   \
                int ch = 2 * g + a_chb;                                               \
                ldmx4(a[mt], A16 + r * 128 + ((ch ^ (r & 7)) << 4));                  \
            }                                                                         \
            _Pragma("unroll")                                                         \
            for (int p = 0; p < 4; ++p) {                                             \
                uint32_t b[4];                                                        \
                int r = wc * 64 + p * 16 + b_nrow;                                    \
                int ch = 2 * g + b_chb;                                               \
                ldmx4(b, Bu[buf] + r * 128 + ((ch ^ (r & 7)) << 4));                  \
                mma_f16(acc[0][2 * p],     a[0], b[0], b[1]);                         \
                mma_f16(acc[0][2 * p + 1], a[0], b[2], b[3]);                         \
                mma_f16(acc[1][2 * p],     a[1], b[0], b[1]);                         \
                mma_f16(acc[1][2 * p + 1], a[1], b[2], b[3]);                         \
            }                                                                         \
        }                                                                             \
    } while (0)

    // ---- prologue ----
    LOAD_B(0, 0);
    LOAD_A32(0, 0);
    asm volatile("cp.async.commit_group;" ::: "memory");
    asm volatile("cp.async.wait_group 0;" ::: "memory");
    __syncthreads();

    // ---- mainloop ----
    #pragma unroll
    for (int c = 0; c < NCHUNK; ++c) {
        int buf = c & 1;
        if (c < NCHUNK - 1) {
            LOAD_B(c + 1, buf ^ 1);
            LOAD_A32(c + 1, buf ^ 1);
            asm volatile("cp.async.commit_group;" ::: "memory");
        }
        CONVERT_A(buf);
        __syncthreads();       // A16 ready for all warps
        COMPUTE(buf);
        if (c < NCHUNK - 1) {
            asm volatile("cp.async.wait_group 0;" ::: "memory");
            __syncthreads();   // next A32/B landed; COMPUTE done -> A16 reusable
        }
    }

    // block 0 reuses pipeline smem for h rows 0..62 — wait until all warps done
    if (blk0) __syncthreads();

    // ---- epilogue: direct register stores (+bias); blk0 rows<63 staged in smem ----
    #pragma unroll
    for (int mt = 0; mt < 2; ++mt) {
        long r0 = row0 + wr * 32 + mt * 16 + q;
        long r1 = r0 + 8;
        #pragma unroll
        for (int nt = 0; nt < 8; ++nt) {
            int j = wc * 64 + nt * 8 + 2 * tig;    // even
            if (j + 1 >= FDIM) continue;
            float* a4 = acc[mt][nt];
            if (r0 < nrows) {
                if (r0 < 63)
                    *reinterpret_cast<float2*>(&h64[r0 * 256 + j]) = make_float2(a4[0], a4[1]);
                else
                    *reinterpret_cast<float2*>(out + r0 * FDIM + j) =
                        make_float2(a4[0] + s_bias[j], a4[1] + s_bias[j + 1]);
            }
            if (r1 < nrows) {
                if (r1 < 63)
                    *reinterpret_cast<float2*>(&h64[r1 * 256 + j]) = make_float2(a4[2], a4[3]);
                else
                    *reinterpret_cast<float2*>(out + r1 * FDIM + j) =
                        make_float2(a4[2] + s_bias[j], a4[3] + s_bias[j + 1]);
            }
        }
    }

    if (!blk0) return;

    // ================= block 0: dense 63x63 attention =================
    __syncthreads();   // h64 visible

    for (int i = wid; i < 63; i += 8) {
        float s1 = 0.f, s2 = 0.f;
        for (int k = lane; k < FDIM; k += 32) {
            float hv = h64[i * 256 + k];
            s1 += hv * att_src[k];
            s2 += hv * att_dst[k];
        }
        #pragma unroll
        for (int o = 16; o > 0; o >>= 1) {
            s1 += __shfl_xor_sync(0xffffffffu, s1, o);
            s2 += __shfl_xor_sync(0xffffffffu, s2, o);
        }
        if (lane == 0) { s_as[i] = s1; s_ad[i] = s2; }
    }
    __syncthreads();

    for (int j = wid; j < 63; j += 8) {
        float ad = s_ad[j];
        float e0 = s_as[lane] + ad;
        e0 = (e0 >= 0.f) ? e0 : NEG_SLOPE * e0;
        float e1 = -3.4e38f;
        if (lane < 31) {
            e1 = s_as[lane + 32] + ad;
            e1 = (e1 >= 0.f) ? e1 : NEG_SLOPE * e1;
        }
        float m = fmaxf(e0, e1);
        #pragma unroll
        for (int o = 16; o > 0; o >>= 1) m = fmaxf(m, __shfl_xor_sync(0xffffffffu, m, o));
        float x0 = expf(e0 - m);
        float x1 = (lane < 31) ? expf(e1 - m) : 0.f;
        float sum = x0 + x1;
        #pragma unroll
        for (int o = 16; o > 0; o >>= 1) sum += __shfl_xor_sync(0xffffffffu, sum, o);
        float inv = 1.f / sum;
        s_alpha[wid][lane]      = x0 * inv;
        s_alpha[wid][lane + 32] = x1 * inv;
        __syncwarp();

        for (int t = lane; t < FDIM; t += 32) {
            float a = 0.f;
            #pragma unroll
            for (int i = 0; i < 63; ++i)
                a = fmaf(s_alpha[wid][i], h64[i * 256 + t], a);
            out[(size_t)j * FDIM + t] = a + s_bias[t];
        }
        __syncwarp();
    }
}

extern "C" void kernel_launch(void* const* d_in, const int* in_sizes, int n_in,
                              void* d_out, int out_size) {
    const float* x       = (const float*)d_in[0];
    const float* W       = (const float*)d_in[1];
    const float* att_src = (const float*)d_in[2];
    const float* att_dst = (const float*)d_in[3];
    const float* bias    = (const float*)d_in[4];
    float* out = (float*)d_out;

    const int nrows = in_sizes[0] / FDIM;                 // 258048
    const int smem_dyn = 2 * 16384 + 8192 + 2 * 32768;    // 104 KB

    static int configured = 0;
    if (!configured) {
        cudaFuncSetAttribute(gemm_h16, cudaFuncAttributeMaxDynamicSharedMemorySize, smem_dyn);
        configured = 1;
    }

    prep_Bh<<<256, 256>>>(W);
    gemm_h16<<<(nrows + BM - 1) / BM, 256, smem_dyn>>>(x, bias, att_src, att_dst, out, nrows);
}